// round 8
// baseline (speedup 1.0000x reference)
#include <cuda_runtime.h>
#include <math.h>
#include <stdint.h>

#define BB 512
#define DD 512
#define LL 24

#define TILE 64
#define KC   16
#define SPLITS 4
#define KSP (DD / SPLITS)   // 128
#define NCHUNK (KSP / KC)   // 8

// Scratch (device globals — no allocations allowed)
__device__ float        g_part[SPLITS][BB * BB];
__device__ float        g_npart[SPLITS][BB];
__device__ unsigned int g_lab[BB];
__device__ float        g_sum;
__device__ unsigned int g_cnt;
__device__ unsigned int g_done;

// Packed dual-FP32 FMA (Blackwell f32x2; base-family PTX, sm_100+)
#define FMA2(acc, a, b) \
    asm("fma.rn.f32x2 %0, %1, %2, %0;" : "+l"(acc) : "l"(a), "l"(b))
#define PACK_DUP(out, f) \
    asm("mov.b64 %0, {%1, %1};" : "=l"(out) : "r"(__float_as_uint(f)))
#define UNPACK2(lo, hi, in) \
    asm("mov.b64 {%0, %1}, %2;" : "=r"(lo), "=r"(hi) : "l"(in))

// ---------------------------------------------------------------------------
// Kernel 1: Gram partials. 64x64 tile, K-split 4 -> 256 blocks x 128 threads.
// Microtile 8 rows (4 packed pairs) x 4 cols = 16 FFMA2 per kk.
// B stored PRE-DUPLICATED in SMEM (u64 lane-pairs) -> inner loop has no packs:
//   2x LDS.128 (a-pairs) + 2x LDS.128 (b-dups) + 16 FFMA2 per kk.
// Double-buffered staging with register prefetch.
// ---------------------------------------------------------------------------
__global__ __launch_bounds__(128) void k_gram(const float* __restrict__ X,
                                              const int* __restrict__ labels) {
    __shared__ float              As[2][KC][TILE + 4];   // row-pair source
    __shared__ unsigned long long Bd[2][KC][TILE];       // dup'd B values

    int tid = threadIdx.x;

    if (blockIdx.x == 0 && blockIdx.y == 0 && blockIdx.z == 0) {
        for (int i = tid; i < BB; i += 128) {
            unsigned m = 0u;
#pragma unroll
            for (int l = 0; l < LL; ++l)
                if (labels[i * LL + l] != 0) m |= (1u << l);
            g_lab[i] = m;
        }
        if (tid == 0) { g_sum = 0.0f; g_cnt = 0u; g_done = 0u; }
    }

    int ty = tid >> 4;          // 0..7  : 8 rows (4 pairs)
    int tx = tid & 15;          // 0..15 : 4 cols
    int rowBase = blockIdx.y * TILE;
    int colBase = blockIdx.x * TILE;
    int z       = blockIdx.z;
    int kBase   = z * KSP;

    // staging coords: 2 float4 per tile per thread
    int sr0 = tid >> 2,           sk0 = (tid & 3) * 4;
    int sr1 = (tid + 128) >> 2,   sk1 = sk0;
    const float* Arow0 = &X[(rowBase + sr0) * DD + kBase];
    const float* Arow1 = &X[(rowBase + sr1) * DD + kBase];
    const float* Brow0 = &X[(colBase + sr0) * DD + kBase];
    const float* Brow1 = &X[(colBase + sr1) * DD + kBase];

    unsigned long long acc[4][4];
#pragma unroll
    for (int p = 0; p < 4; ++p)
#pragma unroll
        for (int c = 0; c < 4; ++c) acc[p][c] = 0ull;

    // preload chunk 0
    float4 pa0 = *reinterpret_cast<const float4*>(&Arow0[sk0]);
    float4 pa1 = *reinterpret_cast<const float4*>(&Arow1[sk1]);
    float4 pb0 = *reinterpret_cast<const float4*>(&Brow0[sk0]);
    float4 pb1 = *reinterpret_cast<const float4*>(&Brow1[sk1]);

#pragma unroll
    for (int c = 0; c < NCHUNK; ++c) {
        int buf = c & 1;
        // store prefetched chunk (B duplicated at staging time)
        As[buf][sk0 + 0][sr0] = pa0.x; As[buf][sk0 + 1][sr0] = pa0.y;
        As[buf][sk0 + 2][sr0] = pa0.z; As[buf][sk0 + 3][sr0] = pa0.w;
        As[buf][sk1 + 0][sr1] = pa1.x; As[buf][sk1 + 1][sr1] = pa1.y;
        As[buf][sk1 + 2][sr1] = pa1.z; As[buf][sk1 + 3][sr1] = pa1.w;
        unsigned long long t;
        PACK_DUP(t, pb0.x); Bd[buf][sk0 + 0][sr0] = t;
        PACK_DUP(t, pb0.y); Bd[buf][sk0 + 1][sr0] = t;
        PACK_DUP(t, pb0.z); Bd[buf][sk0 + 2][sr0] = t;
        PACK_DUP(t, pb0.w); Bd[buf][sk0 + 3][sr0] = t;
        PACK_DUP(t, pb1.x); Bd[buf][sk1 + 0][sr1] = t;
        PACK_DUP(t, pb1.y); Bd[buf][sk1 + 1][sr1] = t;
        PACK_DUP(t, pb1.z); Bd[buf][sk1 + 2][sr1] = t;
        PACK_DUP(t, pb1.w); Bd[buf][sk1 + 3][sr1] = t;
        __syncthreads();

        // issue next chunk's loads (overlap with FMA below)
        if (c + 1 < NCHUNK) {
            int ko = (c + 1) * KC;
            pa0 = *reinterpret_cast<const float4*>(&Arow0[ko + sk0]);
            pa1 = *reinterpret_cast<const float4*>(&Arow1[ko + sk1]);
            pb0 = *reinterpret_cast<const float4*>(&Brow0[ko + sk0]);
            pb1 = *reinterpret_cast<const float4*>(&Brow1[ko + sk1]);
        }

#pragma unroll
        for (int kk = 0; kk < KC; ++kk) {
            const ulonglong2* ap =
                reinterpret_cast<const ulonglong2*>(&As[buf][kk][ty * 8]);
            ulonglong2 a01 = ap[0];
            ulonglong2 a23 = ap[1];
            const ulonglong2* bp =
                reinterpret_cast<const ulonglong2*>(&Bd[buf][kk][tx * 4]);
            ulonglong2 b01 = bp[0];          // dup(col0), dup(col1)
            ulonglong2 b23 = bp[1];          // dup(col2), dup(col3)
            FMA2(acc[0][0], a01.x, b01.x); FMA2(acc[0][1], a01.x, b01.y);
            FMA2(acc[0][2], a01.x, b23.x); FMA2(acc[0][3], a01.x, b23.y);
            FMA2(acc[1][0], a01.y, b01.x); FMA2(acc[1][1], a01.y, b01.y);
            FMA2(acc[1][2], a01.y, b23.x); FMA2(acc[1][3], a01.y, b23.y);
            FMA2(acc[2][0], a23.x, b01.x); FMA2(acc[2][1], a23.x, b01.y);
            FMA2(acc[2][2], a23.x, b23.x); FMA2(acc[2][3], a23.x, b23.y);
            FMA2(acc[3][0], a23.y, b01.x); FMA2(acc[3][1], a23.y, b01.y);
            FMA2(acc[3][2], a23.y, b23.x); FMA2(acc[3][3], a23.y, b23.y);
        }
        __syncthreads();
    }

    // epilogue: 4 row-pairs x 4 cols -> two float4 stores per pair
    int gj = colBase + tx * 4;
#pragma unroll
    for (int p = 0; p < 4; ++p) {
        unsigned lo[4], hi[4];
#pragma unroll
        for (int c = 0; c < 4; ++c) UNPACK2(lo[c], hi[c], acc[p][c]);
        int gi0 = rowBase + ty * 8 + p * 2;
        float4 r0 = make_float4(__uint_as_float(lo[0]), __uint_as_float(lo[1]),
                                __uint_as_float(lo[2]), __uint_as_float(lo[3]));
        float4 r1 = make_float4(__uint_as_float(hi[0]), __uint_as_float(hi[1]),
                                __uint_as_float(hi[2]), __uint_as_float(hi[3]));
        *reinterpret_cast<float4*>(&g_part[z][gi0 * BB + gj])       = r0;
        *reinterpret_cast<float4*>(&g_part[z][(gi0 + 1) * BB + gj]) = r1;
        int d0 = gi0 - gj;
        if ((unsigned)d0 < 4u) g_npart[z][gi0] = (&r0.x)[d0];
        int d1 = gi0 + 1 - gj;
        if ((unsigned)d1 < 4u) g_npart[z][gi0 + 1] = (&r1.x)[d1];
    }
}

// ---------------------------------------------------------------------------
// Kernel 2: triplets. 512 blocks (1 anchor) x 128 threads, ballot compaction.
// ---------------------------------------------------------------------------
__global__ __launch_bounds__(128) void k_tri(float* __restrict__ out) {
    __shared__ float    nd[BB];
    __shared__ int      nn;
    __shared__ float    wsum[4];
    __shared__ unsigned wcnt[4];

    int i    = blockIdx.x;
    int tid  = threadIdx.x;
    int lane = tid & 31;
    int wid  = tid >> 5;

    unsigned mi = g_lab[i];
    float    ni = ((g_npart[0][i] + g_npart[1][i]) + g_npart[2][i]) + g_npart[3][i];
    if (tid == 0) nn = 0;

    float dv[4];
    int   pf[4];
#pragma unroll
    for (int s = 0; s < 4; ++s) {
        int j = s * 128 + tid;
        const float* p = &g_part[0][i * BB + j];
        float G  = ((p[0] + p[BB * BB]) + p[2 * BB * BB]) + p[3 * BB * BB];
        const float* q = &g_npart[0][j];
        float nj = ((q[0] + q[BB]) + q[2 * BB]) + q[3 * BB];
        float sq = ni + nj - 2.0f * G;
        dv[s] = (sq > 0.0f) ? sqrtf(sq) : 0.0f;
        pf[s] = (g_lab[j] & mi) != 0u;
    }
    __syncthreads();

#pragma unroll
    for (int s = 0; s < 4; ++s) {
        unsigned bal = __ballot_sync(0xffffffffu, !pf[s]);
        if (bal) {
            int base = 0;
            if (lane == 0) base = atomicAdd(&nn, __popc(bal));
            base = __shfl_sync(0xffffffffu, base, 0);
            if (!pf[s]) {
                int r = __popc(bal & ((1u << lane) - 1u));
                nd[base + r] = dv[s];
            }
        }
    }
    __syncthreads();

    int N = nn;
    float    lsum = 0.0f;
    unsigned lcnt = 0u;
    if (N > 0) {
#pragma unroll
        for (int s = 0; s < 4; ++s) {
            if (pf[s]) {
                float dj = dv[s];
                for (int k = 0; k < N; ++k) {
                    float v = dj - nd[k];
                    if (v > 1e-16f) { lsum += v; lcnt++; }
                }
            }
        }
    }

#pragma unroll
    for (int off = 16; off; off >>= 1) {
        lsum += __shfl_down_sync(0xffffffffu, lsum, off);
        lcnt += __shfl_down_sync(0xffffffffu, lcnt, off);
    }
    if (lane == 0) { wsum[wid] = lsum; wcnt[wid] = lcnt; }
    __syncthreads();
    if (wid == 0) {
        lsum = (lane < 4) ? wsum[lane] : 0.0f;
        lcnt = (lane < 4) ? wcnt[lane] : 0u;
#pragma unroll
        for (int off = 2; off; off >>= 1) {
            lsum += __shfl_down_sync(0xffffffffu, lsum, off);
            lcnt += __shfl_down_sync(0xffffffffu, lcnt, off);
        }
        if (lane == 0) {
            if (lcnt != 0u || lsum != 0.0f) {
                atomicAdd(&g_sum, lsum);
                atomicAdd(&g_cnt, lcnt);
            }
            __threadfence();
            unsigned prev = atomicAdd(&g_done, 1u);
            if (prev == (unsigned)(BB - 1)) {
                float    s = *((volatile float*)&g_sum);
                unsigned c = *((volatile unsigned*)&g_cnt);
                out[0] = (float)((double)s / ((double)c + 1e-16));
                g_sum = 0.0f; g_cnt = 0u; g_done = 0u;  // reset for replay
            }
        }
    }
}

extern "C" void kernel_launch(void* const* d_in, const int* in_sizes, int n_in,
                              void* d_out, int out_size) {
    const float* src = (const float*)d_in[0];  // (B, D) float32
    const int*   lab = (const int*)d_in[1];    // (B, L) int32

    dim3 grid(BB / TILE, BB / TILE, SPLITS);   // 8 x 8 x 4 = 256 blocks
    k_gram<<<grid, 128>>>(src, lab);
    k_tri<<<BB, 128>>>((float*)d_out);
}

// round 9
// speedup vs baseline: 1.3741x; 1.3741x over previous
#include <cuda_runtime.h>
#include <math.h>
#include <stdint.h>

#define BB 512
#define DD 512
#define LL 24

#define TILE 64
#define KC   16
#define SPLITS 8
#define KSP (DD / SPLITS)   // 64
#define NCHUNK (KSP / KC)   // 4
#define NTILES 36           // upper-triangle 8x8 tile pairs

// Scratch (device globals — no allocations allowed)
__device__ float        g_part[SPLITS][BB * BB];
__device__ float        g_npart[SPLITS][BB];
__device__ unsigned int g_lab[BB];
__device__ float        g_sum;
__device__ unsigned int g_cnt;
__device__ unsigned int g_done;

// upper-triangle tile table (by <= bx)
__device__ const unsigned char TBY[NTILES] = {
    0,0,0,0,0,0,0,0, 1,1,1,1,1,1,1, 2,2,2,2,2,2,
    3,3,3,3,3, 4,4,4,4, 5,5,5, 6,6, 7};
__device__ const unsigned char TBX[NTILES] = {
    0,1,2,3,4,5,6,7, 1,2,3,4,5,6,7, 2,3,4,5,6,7,
    3,4,5,6,7, 4,5,6,7, 5,6,7, 6,7, 7};

// Packed dual-FP32 FMA (Blackwell f32x2; base-family PTX, sm_100+)
#define FMA2(acc, a, b) \
    asm("fma.rn.f32x2 %0, %1, %2, %0;" : "+l"(acc) : "l"(a), "l"(b))
#define PACK_DUP(out, f) \
    asm("mov.b64 %0, {%1, %1};" : "=l"(out) : "r"(__float_as_uint(f)))
#define UNPACK2(lo, hi, in) \
    asm("mov.b64 {%0, %1}, %2;" : "=r"(lo), "=r"(hi) : "l"(in))

// ---------------------------------------------------------------------------
// Kernel 1: Gram partials, symmetric (upper-triangle tiles only).
// 36 tiles x 8 K-splits = 288 blocks x 128 threads (2 CTA/SM).
// Round-7 mainloop: per kk = 2 LDS.128 (a-pairs) + 1 LDS.128 (b) + 4 packs
// + 16 FFMA2. Off-diagonal tiles also write the transposed tile.
// ---------------------------------------------------------------------------
__global__ __launch_bounds__(128) void k_gram(const float* __restrict__ X,
                                              const int* __restrict__ labels) {
    __shared__ float As[2][KC][TILE + 4];
    __shared__ float Bs[2][KC][TILE + 4];

    int tid = threadIdx.x;

    if (blockIdx.x == 0 && blockIdx.y == 0) {
        for (int i = tid; i < BB; i += 128) {
            unsigned m = 0u;
#pragma unroll
            for (int l = 0; l < LL; ++l)
                if (labels[i * LL + l] != 0) m |= (1u << l);
            g_lab[i] = m;
        }
        if (tid == 0) { g_sum = 0.0f; g_cnt = 0u; g_done = 0u; }
    }

    int by = TBY[blockIdx.x];
    int bx = TBX[blockIdx.x];
    int ty = tid >> 4;          // 0..7  : 8 rows (4 pairs)
    int tx = tid & 15;          // 0..15 : 4 cols
    int rowBase = by * TILE;
    int colBase = bx * TILE;
    int z       = blockIdx.y;
    int kBase   = z * KSP;

    // staging coords: 2 float4 per tile per thread
    int sr0 = tid >> 2,           sk0 = (tid & 3) * 4;
    int sr1 = (tid + 128) >> 2;
    const float* Arow0 = &X[(rowBase + sr0) * DD + kBase];
    const float* Arow1 = &X[(rowBase + sr1) * DD + kBase];
    const float* Brow0 = &X[(colBase + sr0) * DD + kBase];
    const float* Brow1 = &X[(colBase + sr1) * DD + kBase];

    unsigned long long acc[4][4];
#pragma unroll
    for (int p = 0; p < 4; ++p)
#pragma unroll
        for (int c = 0; c < 4; ++c) acc[p][c] = 0ull;

    // preload chunk 0
    float4 pa0 = *reinterpret_cast<const float4*>(&Arow0[sk0]);
    float4 pa1 = *reinterpret_cast<const float4*>(&Arow1[sk0]);
    float4 pb0 = *reinterpret_cast<const float4*>(&Brow0[sk0]);
    float4 pb1 = *reinterpret_cast<const float4*>(&Brow1[sk0]);

#pragma unroll
    for (int c = 0; c < NCHUNK; ++c) {
        int buf = c & 1;
        As[buf][sk0 + 0][sr0] = pa0.x; As[buf][sk0 + 1][sr0] = pa0.y;
        As[buf][sk0 + 2][sr0] = pa0.z; As[buf][sk0 + 3][sr0] = pa0.w;
        As[buf][sk0 + 0][sr1] = pa1.x; As[buf][sk0 + 1][sr1] = pa1.y;
        As[buf][sk0 + 2][sr1] = pa1.z; As[buf][sk0 + 3][sr1] = pa1.w;
        Bs[buf][sk0 + 0][sr0] = pb0.x; Bs[buf][sk0 + 1][sr0] = pb0.y;
        Bs[buf][sk0 + 2][sr0] = pb0.z; Bs[buf][sk0 + 3][sr0] = pb0.w;
        Bs[buf][sk0 + 0][sr1] = pb1.x; Bs[buf][sk0 + 1][sr1] = pb1.y;
        Bs[buf][sk0 + 2][sr1] = pb1.z; Bs[buf][sk0 + 3][sr1] = pb1.w;
        __syncthreads();

        if (c + 1 < NCHUNK) {
            int ko = (c + 1) * KC;
            pa0 = *reinterpret_cast<const float4*>(&Arow0[ko + sk0]);
            pa1 = *reinterpret_cast<const float4*>(&Arow1[ko + sk0]);
            pb0 = *reinterpret_cast<const float4*>(&Brow0[ko + sk0]);
            pb1 = *reinterpret_cast<const float4*>(&Brow1[ko + sk0]);
        }

#pragma unroll
        for (int kk = 0; kk < KC; ++kk) {
            const ulonglong2* ap =
                reinterpret_cast<const ulonglong2*>(&As[buf][kk][ty * 8]);
            ulonglong2 a01 = ap[0];
            ulonglong2 a23 = ap[1];
            float4 b4 = *reinterpret_cast<const float4*>(&Bs[buf][kk][tx * 4]);
            unsigned long long B0, B1, B2, B3;
            PACK_DUP(B0, b4.x); PACK_DUP(B1, b4.y);
            PACK_DUP(B2, b4.z); PACK_DUP(B3, b4.w);
            FMA2(acc[0][0], a01.x, B0); FMA2(acc[0][1], a01.x, B1);
            FMA2(acc[0][2], a01.x, B2); FMA2(acc[0][3], a01.x, B3);
            FMA2(acc[1][0], a01.y, B0); FMA2(acc[1][1], a01.y, B1);
            FMA2(acc[1][2], a01.y, B2); FMA2(acc[1][3], a01.y, B3);
            FMA2(acc[2][0], a23.x, B0); FMA2(acc[2][1], a23.x, B1);
            FMA2(acc[2][2], a23.x, B2); FMA2(acc[2][3], a23.x, B3);
            FMA2(acc[3][0], a23.y, B0); FMA2(acc[3][1], a23.y, B1);
            FMA2(acc[3][2], a23.y, B2); FMA2(acc[3][3], a23.y, B3);
        }
        __syncthreads();
    }

    // epilogue: store tile; off-diagonal tiles also store the transpose
    int gj = colBase + tx * 4;
    bool offdiag = (bx != by);
#pragma unroll
    for (int p = 0; p < 4; ++p) {
        unsigned lo[4], hi[4];
#pragma unroll
        for (int c = 0; c < 4; ++c) UNPACK2(lo[c], hi[c], acc[p][c]);
        int gi0 = rowBase + ty * 8 + p * 2;
        float4 r0 = make_float4(__uint_as_float(lo[0]), __uint_as_float(lo[1]),
                                __uint_as_float(lo[2]), __uint_as_float(lo[3]));
        float4 r1 = make_float4(__uint_as_float(hi[0]), __uint_as_float(hi[1]),
                                __uint_as_float(hi[2]), __uint_as_float(hi[3]));
        *reinterpret_cast<float4*>(&g_part[z][gi0 * BB + gj])       = r0;
        *reinterpret_cast<float4*>(&g_part[z][(gi0 + 1) * BB + gj]) = r1;
        if (offdiag) {
#pragma unroll
            for (int c = 0; c < 4; ++c) {
                g_part[z][(gj + c) * BB + gi0]     = (&r0.x)[c];
                g_part[z][(gj + c) * BB + gi0 + 1] = (&r1.x)[c];
            }
        } else {
            int d0 = gi0 - gj;
            if ((unsigned)d0 < 4u) g_npart[z][gi0] = (&r0.x)[d0];
            int d1 = gi0 + 1 - gj;
            if ((unsigned)d1 < 4u) g_npart[z][gi0 + 1] = (&r1.x)[d1];
        }
    }
}

// ---------------------------------------------------------------------------
// Kernel 2: triplets. 512 blocks (1 anchor) x 128 threads, ballot compaction.
// ---------------------------------------------------------------------------
__global__ __launch_bounds__(128) void k_tri(float* __restrict__ out) {
    __shared__ float    nd[BB];
    __shared__ int      nn;
    __shared__ float    wsum[4];
    __shared__ unsigned wcnt[4];

    int i    = blockIdx.x;
    int tid  = threadIdx.x;
    int lane = tid & 31;
    int wid  = tid >> 5;

    unsigned mi = g_lab[i];
    const float* qi = &g_npart[0][i];
    float ni = ((qi[0] + qi[BB]) + (qi[2*BB] + qi[3*BB]))
             + ((qi[4*BB] + qi[5*BB]) + (qi[6*BB] + qi[7*BB]));
    if (tid == 0) nn = 0;

    float dv[4];
    int   pf[4];
#pragma unroll
    for (int s = 0; s < 4; ++s) {
        int j = s * 128 + tid;
        const float* p = &g_part[0][i * BB + j];
        float G = ((p[0] + p[BB*BB]) + (p[2*BB*BB] + p[3*BB*BB]))
                + ((p[4*BB*BB] + p[5*BB*BB]) + (p[6*BB*BB] + p[7*BB*BB]));
        const float* q = &g_npart[0][j];
        float nj = ((q[0] + q[BB]) + (q[2*BB] + q[3*BB]))
                 + ((q[4*BB] + q[5*BB]) + (q[6*BB] + q[7*BB]));
        float sq = ni + nj - 2.0f * G;
        dv[s] = (sq > 0.0f) ? sqrtf(sq) : 0.0f;
        pf[s] = (g_lab[j] & mi) != 0u;
    }
    __syncthreads();

#pragma unroll
    for (int s = 0; s < 4; ++s) {
        unsigned bal = __ballot_sync(0xffffffffu, !pf[s]);
        if (bal) {
            int base = 0;
            if (lane == 0) base = atomicAdd(&nn, __popc(bal));
            base = __shfl_sync(0xffffffffu, base, 0);
            if (!pf[s]) {
                int r = __popc(bal & ((1u << lane) - 1u));
                nd[base + r] = dv[s];
            }
        }
    }
    __syncthreads();

    int N = nn;
    float    lsum = 0.0f;
    unsigned lcnt = 0u;
    if (N > 0) {
#pragma unroll
        for (int s = 0; s < 4; ++s) {
            if (pf[s]) {
                float dj = dv[s];
                for (int k = 0; k < N; ++k) {
                    float v = dj - nd[k];
                    if (v > 1e-16f) { lsum += v; lcnt++; }
                }
            }
        }
    }

#pragma unroll
    for (int off = 16; off; off >>= 1) {
        lsum += __shfl_down_sync(0xffffffffu, lsum, off);
        lcnt += __shfl_down_sync(0xffffffffu, lcnt, off);
    }
    if (lane == 0) { wsum[wid] = lsum; wcnt[wid] = lcnt; }
    __syncthreads();
    if (wid == 0) {
        lsum = (lane < 4) ? wsum[lane] : 0.0f;
        lcnt = (lane < 4) ? wcnt[lane] : 0u;
#pragma unroll
        for (int off = 2; off; off >>= 1) {
            lsum += __shfl_down_sync(0xffffffffu, lsum, off);
            lcnt += __shfl_down_sync(0xffffffffu, lcnt, off);
        }
        if (lane == 0) {
            if (lcnt != 0u || lsum != 0.0f) {
                atomicAdd(&g_sum, lsum);
                atomicAdd(&g_cnt, lcnt);
            }
            __threadfence();
            unsigned prev = atomicAdd(&g_done, 1u);
            if (prev == (unsigned)(BB - 1)) {
                float    s = *((volatile float*)&g_sum);
                unsigned c = *((volatile unsigned*)&g_cnt);
                out[0] = (float)((double)s / ((double)c + 1e-16));
                g_sum = 0.0f; g_cnt = 0u; g_done = 0u;  // reset for replay
            }
        }
    }
}

extern "C" void kernel_launch(void* const* d_in, const int* in_sizes, int n_in,
                              void* d_out, int out_size) {
    const float* src = (const float*)d_in[0];  // (B, D) float32
    const int*   lab = (const int*)d_in[1];    // (B, L) int32

    dim3 grid(NTILES, SPLITS);                 // 36 x 8 = 288 blocks
    k_gram<<<grid, 128>>>(src, lab);
    k_tri<<<BB, 128>>>((float*)d_out);
}